// round 17
// baseline (speedup 1.0000x reference)
#include <cuda_runtime.h>
#include <cstdint>

#define D   48
#define NN  100000
#define NE  1600000
#define NL  6
#define NG  1000

__device__ __align__(16) float g_h[NN * D];
__device__ __align__(16) float g_agg[NN * D];

typedef unsigned long long u64;

// ======================= scalar helpers =====================================
__device__ __forceinline__ u64 pack2(float v) {
    u64 r; asm("mov.b64 %0, {%1, %1};" : "=l"(r) : "f"(v)); return r;
}
__device__ __forceinline__ void unpack2(u64 v, float& lo, float& hi) {
    asm("mov.b64 {%0, %1}, %2;" : "=f"(lo), "=f"(hi) : "l"(v));
}
__device__ __forceinline__ u64 ffma2(u64 a, u64 b, u64 c) {
    u64 d; asm("fma.rn.f32x2 %0, %1, %2, %3;" : "=l"(d) : "l"(a), "l"(b), "l"(c));
    return d;
}
__device__ __forceinline__ float tf32r(float x) {
    float r; asm("cvt.rna.tf32.f32 %0, %1;" : "=f"(r) : "f"(x)); return r;
}

// m16n8k8 tf32 MMA (sm_80+ feature set -> compiles at plain sm_103)
__device__ __forceinline__ void mma8(float* d, const uint32_t* a,
                                     uint32_t b0, uint32_t b1) {
    asm volatile(
        "mma.sync.aligned.m16n8k8.row.col.f32.tf32.tf32.f32 "
        "{%0,%1,%2,%3}, {%4,%5,%6,%7}, {%8,%9}, {%0,%1,%2,%3};"
        : "+f"(d[0]), "+f"(d[1]), "+f"(d[2]), "+f"(d[3])
        : "r"(a[0]), "r"(a[1]), "r"(a[2]), "r"(a[3]), "r"(b0), "r"(b1));
}

// ======================= tensor edge kernel =================================
// smem layout (floats):
#define WS 56                  // W row stride (bank-conflict-free B-frags)
#define XS 52                  // X row stride (bank-conflict-free A-frags)
#define OF_W1H 0
#define OF_W1L 2688
#define OF_W2H 5376
#define OF_W2L 8064
#define OF_B1  10752
#define OF_B2  10800
#define OF_XH  10848
#define OF_XL  (10848 + 128 * XS)     // 17504
#define SMEM_FLOATS (OF_XL + 128 * XS) // 24160
#define SMEM_EDGE_BYTES (SMEM_FLOATS * 4)

// one 3-matrix pass: d += X(plane) * W(plane) over the whole 48-K
__device__ __forceinline__ void mma_pass(float d[2][6][4],
                                         const float* __restrict__ X,
                                         const float* __restrict__ W,
                                         int warp, int r, int c) {
#pragma unroll
    for (int K = 0; K < 6; K++) {
        uint32_t a[2][4];
#pragma unroll
        for (int Rt = 0; Rt < 2; Rt++) {
            int row = warp * 32 + Rt * 16 + r;
            const float* xp = X + row * XS + 8 * K + c;
            a[Rt][0] = __float_as_uint(xp[0]);
            a[Rt][1] = __float_as_uint(xp[8 * XS]);
            a[Rt][2] = __float_as_uint(xp[4]);
            a[Rt][3] = __float_as_uint(xp[8 * XS + 4]);
        }
        const float* wp = W + (8 * K + c) * WS + r;
#pragma unroll
        for (int t = 0; t < 6; t++) {
            uint32_t b0 = __float_as_uint(wp[8 * t]);
            uint32_t b1 = __float_as_uint(wp[4 * WS + 8 * t]);
            mma8(d[0][t], a[0], b0, b1);
            mma8(d[1][t], a[1], b0, b1);
        }
    }
}

__global__ void __launch_bounds__(128)
edge_kernel_mma(const int* __restrict__ edge,
                const float* __restrict__ w1, const float* __restrict__ b1,
                const float* __restrict__ w2, const float* __restrict__ b2) {
    extern __shared__ float sm[];
    int tid = threadIdx.x;
    int lane = tid & 31, warp = tid >> 5;
    int r = lane >> 2, c = lane & 3;
    int base = blockIdx.x * 128;

    // stage weights (hi/lo tf32 split), layout W[k*WS + n]
    for (int idx = tid; idx < D * D; idx += 128) {
        int k = idx / D, n = idx - k * D;
        int o = k * WS + n;
        float v = __ldg(w1 + idx);
        float h = tf32r(v);
        sm[OF_W1H + o] = h;
        sm[OF_W1L + o] = tf32r(v - h);
        v = __ldg(w2 + idx);
        h = tf32r(v);
        sm[OF_W2H + o] = h;
        sm[OF_W2L + o] = tf32r(v - h);
    }
    if (tid < D) { sm[OF_B1 + tid] = b1[tid]; sm[OF_B2 + tid] = b2[tid]; }

    // gather x = h[src]*h[dst] for own row, split into Xh/Xl planes
    {
        int e = base + tid;
        int src = edge[e];
        int dst = edge[NE + e];
        const float4* hs = (const float4*)(g_h + (size_t)src * D);
        const float4* hd = (const float4*)(g_h + (size_t)dst * D);
        float4* xh4 = (float4*)(sm + OF_XH + tid * XS);
        float4* xl4 = (float4*)(sm + OF_XL + tid * XS);
#pragma unroll
        for (int q = 0; q < 12; q++) {
            float4 va = hs[q], vb = hd[q];
            float4 hi, lo;
            float v;
            v = va.x * vb.x; hi.x = tf32r(v); lo.x = tf32r(v - hi.x);
            v = va.y * vb.y; hi.y = tf32r(v); lo.y = tf32r(v - hi.y);
            v = va.z * vb.z; hi.z = tf32r(v); lo.z = tf32r(v - hi.z);
            v = va.w * vb.w; hi.w = tf32r(v); lo.w = tf32r(v - hi.w);
            xh4[q] = hi;
            xl4[q] = lo;
        }
    }
    __syncthreads();

    // ---- layer 1: D1 = Xh*W1h + Xh*W1l + Xl*W1h ----
    float d[2][6][4];
#pragma unroll
    for (int Rt = 0; Rt < 2; Rt++)
#pragma unroll
        for (int t = 0; t < 6; t++)
#pragma unroll
            for (int j = 0; j < 4; j++) d[Rt][t][j] = 0.f;

    mma_pass(d, sm + OF_XH, sm + OF_W1H, warp, r, c);
    mma_pass(d, sm + OF_XH, sm + OF_W1L, warp, r, c);
    mma_pass(d, sm + OF_XL, sm + OF_W1H, warp, r, c);

    __syncthreads();   // everyone done reading X planes before overwrite

    // relu(D1 + b1), re-split into Xh/Xl
#pragma unroll
    for (int Rt = 0; Rt < 2; Rt++) {
        int row0 = warp * 32 + Rt * 16 + r;
#pragma unroll
        for (int t = 0; t < 6; t++) {
            int col = 8 * t + 2 * c;
            float bv0 = sm[OF_B1 + col], bv1 = sm[OF_B1 + col + 1];
#pragma unroll
            for (int rh = 0; rh < 2; rh++) {
                int row = row0 + 8 * rh;
                float v0 = fmaxf(d[Rt][t][2 * rh + 0] + bv0, 0.f);
                float v1 = fmaxf(d[Rt][t][2 * rh + 1] + bv1, 0.f);
                float h0 = tf32r(v0), h1 = tf32r(v1);
                *(float2*)(sm + OF_XH + row * XS + col) = make_float2(h0, h1);
                *(float2*)(sm + OF_XL + row * XS + col) =
                    make_float2(tf32r(v0 - h0), tf32r(v1 - h1));
            }
        }
    }
    __syncthreads();

    // ---- layer 2 ----
#pragma unroll
    for (int Rt = 0; Rt < 2; Rt++)
#pragma unroll
        for (int t = 0; t < 6; t++)
#pragma unroll
            for (int j = 0; j < 4; j++) d[Rt][t][j] = 0.f;

    mma_pass(d, sm + OF_XH, sm + OF_W2H, warp, r, c);
    mma_pass(d, sm + OF_XH, sm + OF_W2L, warp, r, c);
    mma_pass(d, sm + OF_XL, sm + OF_W2H, warp, r, c);

    // epilogue: + b2, scatter-add to g_agg[dst]
#pragma unroll
    for (int Rt = 0; Rt < 2; Rt++) {
#pragma unroll
        for (int rh = 0; rh < 2; rh++) {
            int row = warp * 32 + Rt * 16 + r + 8 * rh;
            int dd = edge[NE + base + row];
            float* ag = g_agg + (size_t)dd * D;
#pragma unroll
            for (int t = 0; t < 6; t++) {
                int col = 8 * t + 2 * c;
                float v0 = d[Rt][t][2 * rh + 0] + sm[OF_B2 + col];
                float v1 = d[Rt][t][2 * rh + 1] + sm[OF_B2 + col + 1];
                asm volatile("red.global.add.v2.f32 [%0], {%1, %2};"
                             :: "l"(ag + col), "f"(v0), "f"(v1) : "memory");
            }
        }
    }
}

// =================== scalar update path (R9, measured best) =================
__device__ __forceinline__ void mlp2_gemm(float* __restrict__ s_x,
                                          const float* __restrict__ s_w1,
                                          const float* __restrict__ s_b1,
                                          const float* __restrict__ s_w2,
                                          const float* __restrict__ s_b2,
                                          int a, int b,
                                          float* __restrict__ m) {
    u64 acc[4][6];
    {
        const u64* bp = (const u64*)(s_b1 + b * 12);
        u64 b0 = bp[0], b1 = bp[1], b2 = bp[2], b3 = bp[3], b4 = bp[4], b5 = bp[5];
#pragma unroll
        for (int e = 0; e < 4; e++) {
            acc[e][0] = b0; acc[e][1] = b1; acc[e][2] = b2;
            acc[e][3] = b3; acc[e][4] = b4; acc[e][5] = b5;
        }
    }
#pragma unroll 4
    for (int i = 0; i < D; i++) {
        const ulonglong2* w = (const ulonglong2*)(s_w1 + i * D + b * 12);
        ulonglong2 wa = w[0], wb = w[1], wc = w[2];
        const float* xr = s_x + i * 128 + a;
        float x0 = xr[0], x1 = xr[32], x2 = xr[64], x3 = xr[96];
        u64 xx;
        xx = pack2(x0);
        acc[0][0] = ffma2(xx, wa.x, acc[0][0]); acc[0][1] = ffma2(xx, wa.y, acc[0][1]);
        acc[0][2] = ffma2(xx, wb.x, acc[0][2]); acc[0][3] = ffma2(xx, wb.y, acc[0][3]);
        acc[0][4] = ffma2(xx, wc.x, acc[0][4]); acc[0][5] = ffma2(xx, wc.y, acc[0][5]);
        xx = pack2(x1);
        acc[1][0] = ffma2(xx, wa.x, acc[1][0]); acc[1][1] = ffma2(xx, wa.y, acc[1][1]);
        acc[1][2] = ffma2(xx, wb.x, acc[1][2]); acc[1][3] = ffma2(xx, wb.y, acc[1][3]);
        acc[1][4] = ffma2(xx, wc.x, acc[1][4]); acc[1][5] = ffma2(xx, wc.y, acc[1][5]);
        xx = pack2(x2);
        acc[2][0] = ffma2(xx, wa.x, acc[2][0]); acc[2][1] = ffma2(xx, wa.y, acc[2][1]);
        acc[2][2] = ffma2(xx, wb.x, acc[2][2]); acc[2][3] = ffma2(xx, wb.y, acc[2][3]);
        acc[2][4] = ffma2(xx, wc.x, acc[2][4]); acc[2][5] = ffma2(xx, wc.y, acc[2][5]);
        xx = pack2(x3);
        acc[3][0] = ffma2(xx, wa.x, acc[3][0]); acc[3][1] = ffma2(xx, wa.y, acc[3][1]);
        acc[3][2] = ffma2(xx, wb.x, acc[3][2]); acc[3][3] = ffma2(xx, wb.y, acc[3][3]);
        acc[3][4] = ffma2(xx, wc.x, acc[3][4]); acc[3][5] = ffma2(xx, wc.y, acc[3][5]);
    }

    __syncthreads();
#pragma unroll
    for (int e = 0; e < 4; e++) {
        float* col = s_x + 32 * e + a;
#pragma unroll
        for (int k = 0; k < 6; k++) {
            float lo, hi; unpack2(acc[e][k], lo, hi);
            col[(b * 12 + 2 * k) * 128]     = fmaxf(lo, 0.f);
            col[(b * 12 + 2 * k + 1) * 128] = fmaxf(hi, 0.f);
        }
    }
    __syncthreads();

    {
        const u64* bp = (const u64*)(s_b2 + b * 12);
        u64 b0 = bp[0], b1 = bp[1], b2 = bp[2], b3 = bp[3], b4 = bp[4], b5 = bp[5];
#pragma unroll
        for (int e = 0; e < 4; e++) {
            acc[e][0] = b0; acc[e][1] = b1; acc[e][2] = b2;
            acc[e][3] = b3; acc[e][4] = b4; acc[e][5] = b5;
        }
    }
#pragma unroll 4
    for (int i = 0; i < D; i++) {
        const ulonglong2* w = (const ulonglong2*)(s_w2 + i * D + b * 12);
        ulonglong2 wa = w[0], wb = w[1], wc = w[2];
        const float* xr = s_x + i * 128 + a;
        float x0 = xr[0], x1 = xr[32], x2 = xr[64], x3 = xr[96];
        u64 xx;
        xx = pack2(x0);
        acc[0][0] = ffma2(xx, wa.x, acc[0][0]); acc[0][1] = ffma2(xx, wa.y, acc[0][1]);
        acc[0][2] = ffma2(xx, wb.x, acc[0][2]); acc[0][3] = ffma2(xx, wb.y, acc[0][3]);
        acc[0][4] = ffma2(xx, wc.x, acc[0][4]); acc[0][5] = ffma2(xx, wc.y, acc[0][5]);
        xx = pack2(x1);
        acc[1][0] = ffma2(xx, wa.x, acc[1][0]); acc[1][1] = ffma2(xx, wa.y, acc[1][1]);
        acc[1][2] = ffma2(xx, wb.x, acc[1][2]); acc[1][3] = ffma2(xx, wb.y, acc[1][3]);
        acc[1][4] = ffma2(xx, wc.x, acc[1][4]); acc[1][5] = ffma2(xx, wc.y, acc[1][5]);
        xx = pack2(x2);
        acc[2][0] = ffma2(xx, wa.x, acc[2][0]); acc[2][1] = ffma2(xx, wa.y, acc[2][1]);
        acc[2][2] = ffma2(xx, wb.x, acc[2][2]); acc[2][3] = ffma2(xx, wb.y, acc[2][3]);
        acc[2][4] = ffma2(xx, wc.x, acc[2][4]); acc[2][5] = ffma2(xx, wc.y, acc[2][5]);
        xx = pack2(x3);
        acc[3][0] = ffma2(xx, wa.x, acc[3][0]); acc[3][1] = ffma2(xx, wa.y, acc[3][1]);
        acc[3][2] = ffma2(xx, wb.x, acc[3][2]); acc[3][3] = ffma2(xx, wb.y, acc[3][3]);
        acc[3][4] = ffma2(xx, wc.x, acc[3][4]); acc[3][5] = ffma2(xx, wc.y, acc[3][5]);
    }

#pragma unroll
    for (int e = 0; e < 4; e++)
#pragma unroll
        for (int k = 0; k < 6; k++)
            unpack2(acc[e][k], m[e * 12 + 2 * k], m[e * 12 + 2 * k + 1]);
}

__device__ __forceinline__ void mlp_hidden_reg(const float* x, const float* s_w1,
                                               const float* s_b1, float* r) {
    u64 acc[24];
    const u64* bp = (const u64*)s_b1;
#pragma unroll
    for (int k = 0; k < 24; k++) acc[k] = bp[k];
#pragma unroll 8
    for (int i = 0; i < D; i++) {
        u64 xx = pack2(x[i]);
        const ulonglong2* w = (const ulonglong2*)(s_w1 + i * D);
#pragma unroll
        for (int k = 0; k < 12; k++) {
            ulonglong2 ww = w[k];
            acc[2 * k]     = ffma2(xx, ww.x, acc[2 * k]);
            acc[2 * k + 1] = ffma2(xx, ww.y, acc[2 * k + 1]);
        }
    }
#pragma unroll
    for (int k = 0; k < 24; k++) {
        float lo, hi; unpack2(acc[k], lo, hi);
        r[2 * k]     = fmaxf(lo, 0.f);
        r[2 * k + 1] = fmaxf(hi, 0.f);
    }
}

__global__ void __launch_bounds__(128) embed_kernel(const int* __restrict__ an,
                                                    const float* __restrict__ emb) {
    int n = blockIdx.x * 128 + threadIdx.x;
    if (n >= NN) return;
    const float4* e = (const float4*)(emb + (size_t)an[n] * D);
    float4* hp = (float4*)(g_h + (size_t)n * D);
#pragma unroll
    for (int q = 0; q < 12; q++) hp[q] = e[q];
}

__global__ void __launch_bounds__(256) zero_agg_kernel() {
    int t = blockIdx.x * 256 + threadIdx.x;
    if (t < NN * D / 4) ((float4*)g_agg)[t] = make_float4(0.f, 0.f, 0.f, 0.f);
}

__global__ void __launch_bounds__(256) zero_out_kernel(float* out) {
    int t = blockIdx.x * 256 + threadIdx.x;
    if (t < NG) out[t] = 0.f;
}

// update: reads g_agg, then zeroes it (so next layer's edge scatter starts clean)
__global__ void __launch_bounds__(128) update_kernel(const float* __restrict__ w1,
                                                     const float* __restrict__ b1,
                                                     const float* __restrict__ w2,
                                                     const float* __restrict__ b2) {
    __shared__ __align__(16) float s_w1[D * D];
    __shared__ __align__(16) float s_w2[D * D];
    __shared__ __align__(16) float s_b1[D];
    __shared__ __align__(16) float s_b2[D];
    __shared__ __align__(16) float s_x[D * 128];

    int tid = threadIdx.x;
    for (int t = tid; t < D * D; t += 128) { s_w1[t] = w1[t]; s_w2[t] = w2[t]; }
    if (tid < D) { s_b1[tid] = b1[tid]; s_b2[tid] = b2[tid]; }

    int base = blockIdx.x * 128;
    {
        int n = base + tid;
        float* col = s_x + tid;
        if (n < NN) {
            float4* ap = (float4*)(g_agg + (size_t)n * D);
            float4 z = make_float4(0.f, 0.f, 0.f, 0.f);
#pragma unroll
            for (int q = 0; q < 12; q++) {
                float4 v = ap[q];
                ap[q] = z;               // zero for next layer
                col[(4 * q + 0) * 128] = v.x;
                col[(4 * q + 1) * 128] = v.y;
                col[(4 * q + 2) * 128] = v.z;
                col[(4 * q + 3) * 128] = v.w;
            }
        } else {
#pragma unroll
            for (int q = 0; q < D; q++) col[q * 128] = 0.f;
        }
    }
    __syncthreads();

    int a = tid & 31, b = tid >> 5;
    float u[48];
    mlp2_gemm(s_x, s_w1, s_b1, s_w2, s_b2, a, b, u);

#pragma unroll
    for (int e = 0; e < 4; e++) {
        int n = base + 32 * e + a;
        if (n < NN) {
            float4* hp = (float4*)(g_h + (size_t)n * D + b * 12);
#pragma unroll
            for (int q = 0; q < 3; q++) {
                float4 hv = hp[q];
                hv.x += u[e * 12 + 4 * q + 0];
                hv.y += u[e * 12 + 4 * q + 1];
                hv.z += u[e * 12 + 4 * q + 2];
                hv.w += u[e * 12 + 4 * q + 3];
                hp[q] = hv;
            }
        }
    }
}

__global__ void __launch_bounds__(128) readout_kernel(const float* __restrict__ w1,
                                                      const float* __restrict__ b1,
                                                      const float* __restrict__ w2v,
                                                      const float* __restrict__ b2s,
                                                      const int* __restrict__ gid,
                                                      float* __restrict__ out) {
    __shared__ __align__(16) float s_w1[D * D];
    __shared__ __align__(16) float s_b1[D];
    __shared__ __align__(16) float s_w2[D];
    __shared__ float s_b2;
    for (int t = threadIdx.x; t < D * D; t += 128) s_w1[t] = w1[t];
    if (threadIdx.x < D) { s_b1[threadIdx.x] = b1[threadIdx.x]; s_w2[threadIdx.x] = w2v[threadIdx.x]; }
    if (threadIdx.x == 0) s_b2 = b2s[0];
    __syncthreads();

    int n = blockIdx.x * 128 + threadIdx.x;
    if (n >= NN) return;

    const float4* hp = (const float4*)(g_h + (size_t)n * D);
    float x[D];
#pragma unroll
    for (int q = 0; q < 12; q++) {
        float4 v = hp[q];
        x[4 * q + 0] = v.x; x[4 * q + 1] = v.y; x[4 * q + 2] = v.z; x[4 * q + 3] = v.w;
    }

    float r[D];
    mlp_hidden_reg(x, s_w1, s_b1, r);

    float y = s_b2;
#pragma unroll
    for (int k = 0; k < D; k++) y += r[k] * s_w2[k];

    atomicAdd(&out[gid[n]], y);
}

extern "C" void kernel_launch(void* const* d_in, const int* in_sizes, int n_in,
                              void* d_out, int out_size) {
    const int*   AtomicNum = (const int*)d_in[0];
    const int*   Edge      = (const int*)d_in[1];
    const int*   graph_id  = (const int*)d_in[2];
    const float* emb       = (const float*)d_in[3];
    const float* msg_w1    = (const float*)d_in[4];
    const float* msg_b1    = (const float*)d_in[5];
    const float* msg_w2    = (const float*)d_in[6];
    const float* msg_b2    = (const float*)d_in[7];
    const float* upd_w1    = (const float*)d_in[8];
    const float* upd_b1    = (const float*)d_in[9];
    const float* upd_w2    = (const float*)d_in[10];
    const float* upd_b2    = (const float*)d_in[11];
    const float* ro_w1     = (const float*)d_in[12];
    const float* ro_b1     = (const float*)d_in[13];
    const float* ro_w2     = (const float*)d_in[14];
    const float* ro_b2     = (const float*)d_in[15];
    float* out = (float*)d_out;

    cudaFuncSetAttribute(edge_kernel_mma,
                         cudaFuncAttributeMaxDynamicSharedMemorySize, SMEM_EDGE_BYTES);

    embed_kernel<<<(NN + 127) / 128, 128>>>(AtomicNum, emb);

    const int zero_blocks = (NN * D / 4 + 255) / 256;
    const int edge_blocks = NE / 128;           // 12500
    const int node_blocks = (NN + 127) / 128;   // 782

    zero_agg_kernel<<<zero_blocks, 256>>>();    // once; updates re-zero per layer

    for (int l = 0; l < NL; l++) {
        edge_kernel_mma<<<edge_blocks, 128, SMEM_EDGE_BYTES>>>(Edge,
                                          msg_w1 + (size_t)l * D * D, msg_b1 + (size_t)l * D,
                                          msg_w2 + (size_t)l * D * D, msg_b2 + (size_t)l * D);
        update_kernel<<<node_blocks, 128>>>(upd_w1 + (size_t)l * D * D, upd_b1 + (size_t)l * D,
                                            upd_w2 + (size_t)l * D * D, upd_b2 + (size_t)l * D);
    }

    zero_out_kernel<<<(NG + 255) / 256, 256>>>(out);
    readout_kernel<<<node_blocks, 128>>>(ro_w1, ro_b1, ro_w2, ro_b2, graph_id, out);
}